// round 6
// baseline (speedup 1.0000x reference)
#include <cuda_runtime.h>
#include <cstdint>
#include <math.h>

// ---------------- problem constants ----------------
#define BB   64
#define NN   197
#define CC   768
#define HH   12
#define DHD  64
#define MM   3072
#define NT   (BB*NN)        // 12608 tokens
#define NPX  (BB*(NN-1))    // 12544 non-cls tokens
#define CQ   (3*CC)         // 2304

// ---------------- scratch (static device memory; no allocation) ----------------
__device__ float g_XN  [NT*CC];
__device__ float g_QKV [NT*CQ];
__device__ float g_S   [(size_t)BB*HH*NN*NN];
__device__ float g_AO  [NT*CC];
__device__ float g_MLP1[NT*MM];
__device__ float g_PH  [NPX*CC];
__device__ float g_PH2 [NPX*CC];
__device__ float g_PCAT[NPX*CC];
__device__ float g_PH3 [NPX*(CC/2)];
__device__ float g_PH4 [NPX*(CC/4)];
__device__ float g_LOG [NPX*2];
__device__ float g_GLOB[BB*(CC/2)];
__device__ float g_PREV[NPX];
__device__ float g_DFULL[BB*NN];

// ---------------- threefry-2x32 (matches JAX exactly) ----------------
__host__ __device__ __forceinline__ unsigned rotl32(unsigned v, int d) {
    return (v << d) | (v >> (32 - d));
}
__host__ __device__ __forceinline__ void tf2x32(unsigned k0, unsigned k1,
                                                unsigned x0, unsigned x1,
                                                unsigned& o0, unsigned& o1) {
    unsigned ks2 = k0 ^ k1 ^ 0x1BD11BDAu;
    x0 += k0; x1 += k1;
#define TF_RND(r) { x0 += x1; x1 = rotl32(x1, r); x1 ^= x0; }
    TF_RND(13) TF_RND(15) TF_RND(26) TF_RND(6)   x0 += k1;  x1 += ks2 + 1u;
    TF_RND(17) TF_RND(29) TF_RND(16) TF_RND(24)  x0 += ks2; x1 += k0  + 2u;
    TF_RND(13) TF_RND(15) TF_RND(26) TF_RND(6)   x0 += k0;  x1 += k1  + 3u;
    TF_RND(17) TF_RND(29) TF_RND(16) TF_RND(24)  x0 += k1;  x1 += ks2 + 4u;
    TF_RND(13) TF_RND(15) TF_RND(26) TF_RND(6)   x0 += ks2; x1 += k0  + 5u;
#undef TF_RND
    o0 = x0; o1 = x1;
}

// JAX partitionable threefry (default since jax 0.4.36):
// per-element 64-bit counter e -> (bits1, bits2) = threefry2x32(key, (e>>32, e&0xffffffff));
// for bit_width==32 the random bits are bits1 ^ bits2.
__device__ __forceinline__ float jax_uniform_elem(unsigned k0, unsigned k1, unsigned e) {
    unsigned o0, o1;
    tf2x32(k0, k1, 0u, e, o0, o1);
    unsigned bits = o0 ^ o1;
    unsigned u = (bits >> 9) | 0x3f800000u;
    float f = __uint_as_float(u) - 1.0f;       // [0,1)
    // JAX: max(minval, f*(maxval-minval) + minval); (1.0f-1e-10f)==1.0f in fp32
    return fmaxf(1e-10f, __fadd_rn(f, 1e-10f));
}

// ---------------- helpers ----------------
__device__ __forceinline__ float block_sum256(float v, float* red) {
    int tid = threadIdx.x;
    red[tid] = v; __syncthreads();
    #pragma unroll
    for (int s = 128; s > 0; s >>= 1) {
        if (tid < s) red[tid] += red[tid + s];
        __syncthreads();
    }
    float r = red[0]; __syncthreads();
    return r;
}
__device__ __forceinline__ float block_max256(float v, float* red) {
    int tid = threadIdx.x;
    red[tid] = v; __syncthreads();
    #pragma unroll
    for (int s = 128; s > 0; s >>= 1) {
        if (tid < s) red[tid] = fmaxf(red[tid], red[tid + s]);
        __syncthreads();
    }
    float r = red[0]; __syncthreads();
    return r;
}
__device__ __forceinline__ float gelu_exact(float v) {
    return 0.5f * v * (1.0f + erff(v * 0.70710678118654752440f));
}

// ---------------- kernels ----------------
__global__ void init_prev_kernel(float* prev) {
    int t = blockIdx.x * blockDim.x + threadIdx.x;
    if (t < NPX) prev[t] = 1.0f;
}

// LayerNorm over C=768. 256 threads/block, 3 elems/thread. mode 1: skip cls rows.
__global__ void ln_kernel(const float* __restrict__ in, const float* __restrict__ g,
                          const float* __restrict__ bta, float* __restrict__ out, int mode) {
    int r = blockIdx.x;
    int ir = r;
    if (mode == 1) { int b = r / 196, j = r % 196; ir = b * NN + 1 + j; }
    const float* x = in + (size_t)ir * CC;
    int tid = threadIdx.x;
    __shared__ float red[256];
    float v0 = x[tid], v1 = x[tid + 256], v2 = x[tid + 512];
    float total = block_sum256(v0 + v1 + v2, red);
    float mu = total * (1.0f / CC);
    float d0 = v0 - mu, d1 = v1 - mu, d2 = v2 - mu;
    float tot2 = block_sum256(d0*d0 + d1*d1 + d2*d2, red);
    float rstd = rsqrtf(tot2 * (1.0f / CC) + 1e-5f);
    float* o = out + (size_t)r * CC;
    o[tid]       = d0 * rstd * g[tid]       + bta[tid];
    o[tid + 256] = d1 * rstd * g[tid + 256] + bta[tid + 256];
    o[tid + 512] = d2 * rstd * g[tid + 512] + bta[tid + 512];
}

// generic SGEMM: out[M,N] = A[M,K] @ W[K,N] + bias ; ACT==1 -> GELU ; RES -> += res
template<int ACT, int RES>
__global__ void sgemm(const float* __restrict__ A, const float* __restrict__ W,
                      const float* __restrict__ bias, const float* __restrict__ res,
                      float* __restrict__ out, int M, int N, int K) {
    __shared__ float As[16][65];
    __shared__ float Bs[16][65];
    int tid = threadIdx.x;
    int row0 = blockIdx.y * 64, col0 = blockIdx.x * 64;
    int tx = tid & 15, ty = tid >> 4;
    float acc[4][4] = {};
    for (int k0 = 0; k0 < K; k0 += 16) {
        #pragma unroll
        for (int i = 0; i < 4; i++) {
            int m = (tid >> 4) + i * 16;
            int k = tid & 15;
            int gr = row0 + m;
            As[k][m] = (gr < M) ? A[(size_t)gr * K + k0 + k] : 0.0f;
        }
        #pragma unroll
        for (int i = 0; i < 4; i++) {
            int k = (tid >> 6) + i * 4;
            int n = tid & 63;
            int gc = col0 + n;
            Bs[k][n] = (gc < N) ? W[(size_t)(k0 + k) * N + gc] : 0.0f;
        }
        __syncthreads();
        #pragma unroll
        for (int k = 0; k < 16; k++) {
            float a[4], b[4];
            #pragma unroll
            for (int i = 0; i < 4; i++) a[i] = As[k][ty * 4 + i];
            #pragma unroll
            for (int j = 0; j < 4; j++) b[j] = Bs[k][tx * 4 + j];
            #pragma unroll
            for (int i = 0; i < 4; i++)
                #pragma unroll
                for (int j = 0; j < 4; j++) acc[i][j] = fmaf(a[i], b[j], acc[i][j]);
        }
        __syncthreads();
    }
    #pragma unroll
    for (int i = 0; i < 4; i++) {
        int r = row0 + ty * 4 + i;
        if (r >= M) continue;
        #pragma unroll
        for (int j = 0; j < 4; j++) {
            int c = col0 + tx * 4 + j;
            if (c >= N) continue;
            float v = acc[i][j] + bias[c];
            if (ACT == 1) v = gelu_exact(v);
            if (RES) v += res[(size_t)r * N + c];
            out[(size_t)r * N + c] = v;
        }
    }
}

// scores: S[b,h,q,k] = q_vec . k_vec  (raw dot; scale+mask in softmax)
__global__ void scores_kernel(const float* __restrict__ qkv, float* __restrict__ S) {
    int bh = blockIdx.z; int b = bh / HH, h = bh % HH;
    int q0 = blockIdx.x * 32, k0 = blockIdx.y * 32;
    __shared__ float Qs[32][17];
    __shared__ float Ks[32][17];
    int tid = threadIdx.x;
    int tx = tid & 15, ty = tid >> 4;
    float acc[2][2] = {};
    for (int d0 = 0; d0 < DHD; d0 += 16) {
        #pragma unroll
        for (int i = 0; i < 2; i++) {
            int idx = tid + i * 256;
            int ri = idx >> 4, dd = idx & 15;
            int q = q0 + ri;
            Qs[ri][dd] = (q < NN) ? qkv[(size_t)(b * NN + q) * CQ + h * DHD + d0 + dd] : 0.0f;
            int k = k0 + ri;
            Ks[ri][dd] = (k < NN) ? qkv[(size_t)(b * NN + k) * CQ + CC + h * DHD + d0 + dd] : 0.0f;
        }
        __syncthreads();
        #pragma unroll
        for (int dd = 0; dd < 16; dd++) {
            float qa0 = Qs[ty * 2][dd],     qa1 = Qs[ty * 2 + 1][dd];
            float kb0 = Ks[tx * 2][dd],     kb1 = Ks[tx * 2 + 1][dd];
            acc[0][0] = fmaf(qa0, kb0, acc[0][0]);
            acc[0][1] = fmaf(qa0, kb1, acc[0][1]);
            acc[1][0] = fmaf(qa1, kb0, acc[1][0]);
            acc[1][1] = fmaf(qa1, kb1, acc[1][1]);
        }
        __syncthreads();
    }
    #pragma unroll
    for (int i = 0; i < 2; i++) {
        int q = q0 + ty * 2 + i;
        if (q >= NN) continue;
        #pragma unroll
        for (int j = 0; j < 2; j++) {
            int k = k0 + tx * 2 + j;
            if (k >= NN) continue;
            S[(((size_t)bh * NN) + q) * NN + k] = acc[i][j];
        }
    }
}

// softmax over k with scale 0.125 and drop-mask (exact -1e9 like reference)
__global__ void softmax_kernel(float* __restrict__ S, const float* __restrict__ dfull,
                               int mask_active) {
    int rid = blockIdx.x;                 // (b*H+h)*N + q
    int q = rid % NN; int bh = rid / NN; int b = bh / HH;
    float* row = S + (size_t)rid * NN;
    int tid = threadIdx.x;
    __shared__ float red[256];
    float dq = mask_active ? dfull[b * NN + q] : 1.0f;
    float val = -3.0e38f;
    if (tid < NN) {
        float raw = row[tid] * 0.125f;
        bool keep = true;
        if (mask_active) keep = (tid == q) || (dq > 0.0f && dfull[b * NN + tid] > 0.0f);
        val = keep ? raw : -1e9f;
    }
    float m = block_max256(val, red);
    float e = (tid < NN) ? expf(val - m) : 0.0f;
    float s = block_sum256(e, red);
    if (tid < NN) row[tid] = e / s;
}

// attn @ V : AO[b,q,h*64+d] = sum_k P[b,h,q,k] * V[b,k,h*64+d]
__global__ void av_kernel(const float* __restrict__ P, const float* __restrict__ qkv,
                          float* __restrict__ AO) {
    size_t t = (size_t)blockIdx.x * blockDim.x + threadIdx.x;
    if (t >= (size_t)NT * CC) return;
    int col = (int)(t % CC); int rowt = (int)(t / CC);
    int b = rowt / NN, q = rowt % NN;
    int h = col / DHD;
    const float* prow = P + ((size_t)(b * HH + h) * NN + q) * NN;
    const float* vcol = qkv + (size_t)(b * NN) * CQ + 2 * CC + col;
    float acc = 0.0f;
    for (int k = 0; k < NN; k++) acc = fmaf(prow[k], vcol[(size_t)k * CQ], acc);
    AO[(size_t)rowt * CC + col] = acc;
}

// predictor: glob[b,c] = sum_j h2[b,j,384+c]*prev[b,j] / (sum_j prev[b,j] + 1e-20)
__global__ void glob_kernel(const float* __restrict__ ph2, const float* __restrict__ prev,
                            float* __restrict__ glob) {
    int b = blockIdx.x;
    int tid = threadIdx.x;
    __shared__ float red[256];
    float pv = (tid < 196) ? prev[b * 196 + tid] : 0.0f;
    float psum = block_sum256(pv, red);
    float denom = psum + 1e-20f;
    for (int c = tid; c < 384; c += 256) {
        float acc = 0.0f;
        for (int j = 0; j < 196; j++)
            acc = fmaf(ph2[((size_t)(b * 196 + j)) * CC + 384 + c], prev[b * 196 + j], acc);
        glob[b * 384 + c] = acc / denom;
    }
}

__global__ void concat_kernel(const float* __restrict__ ph2, const float* __restrict__ glob,
                              float* __restrict__ pcat) {
    size_t t = (size_t)blockIdx.x * blockDim.x + threadIdx.x;
    if (t >= (size_t)NPX * CC) return;
    int c = (int)(t % CC); int row = (int)(t / CC); int b = row / 196;
    pcat[t] = (c < 384) ? ph2[(size_t)row * CC + c] : glob[b * 384 + (c - 384)];
}

// logits: one warp per token; PH4[t,0:192] @ w3[192,2] + b3
__global__ void logits_kernel(const float* __restrict__ ph4, const float* __restrict__ w,
                              const float* __restrict__ bias, float* __restrict__ out) {
    int warp = (blockIdx.x * blockDim.x + threadIdx.x) >> 5;
    int lane = threadIdx.x & 31;
    if (warp >= NPX) return;
    const float* row = ph4 + (size_t)warp * 192;
    float a0 = 0.0f, a1 = 0.0f;
    for (int c = lane; c < 192; c += 32) {
        float h = row[c];
        a0 = fmaf(h, w[c * 2], a0);
        a1 = fmaf(h, w[c * 2 + 1], a1);
    }
    #pragma unroll
    for (int o = 16; o > 0; o >>= 1) {
        a0 += __shfl_down_sync(0xffffffffu, a0, o);
        a1 += __shfl_down_sync(0xffffffffu, a1, o);
    }
    if (lane == 0) {
        out[warp * 2]     = a0 + bias[0];
        out[warp * 2 + 1] = a1 + bias[1];
    }
}

// gumbel decision: updates prev + dfull
__global__ void decision_kernel(const float* __restrict__ logits, float* __restrict__ prev,
                                float* __restrict__ dfull, unsigned k0, unsigned k1) {
    int t = blockIdx.x * blockDim.x + threadIdx.x;
    if (t >= NPX) return;
    int b = t / 196, j = t % 196;
    float l0 = logits[t * 2], l1 = logits[t * 2 + 1];
    float m = fmaxf(l0, l1);
    float e0 = expf(l0 - m), e1 = expf(l1 - m);
    float inv = 1.0f / (e0 + e1);
    float s0 = e0 * inv, s1 = e1 * inv;
    float u0 = jax_uniform_elem(k0, k1, (unsigned)(2 * t));
    float u1 = jax_uniform_elem(k0, k1, (unsigned)(2 * t + 1));
    float g0 = -logf(-logf(u0));
    float g1 = -logf(-logf(u1));
    float a0 = s0 + g0, a1 = s1 + g1;
    float hard1 = (a1 > a0) ? 1.0f : 0.0f;
    float m2 = fmaxf(a0, a1);
    float y0e = expf(a0 - m2), y1e = expf(a1 - m2);
    float ys1 = y1e / (y0e + y1e);
    float y1 = (hard1 + ys1) - ys1;   // straight-through forward value
    float dec = y1 * prev[t];
    prev[t] = dec;
    dfull[b * NN + 1 + j] = dec;
    if (j == 0) dfull[b * NN] = 1.0f;
}

// ---------------- host orchestration ----------------
extern "C" void kernel_launch(void* const* d_in, const int* in_sizes, int n_in,
                              void* d_out, int out_size) {
    const float* x_in   = (const float*)d_in[0];
    const float* ln1_g  = (const float*)d_in[1];
    const float* ln1_b  = (const float*)d_in[2];
    const float* qkv_w  = (const float*)d_in[3];
    const float* qkv_b  = (const float*)d_in[4];
    const float* proj_w = (const float*)d_in[5];
    const float* proj_b = (const float*)d_in[6];
    const float* ln2_g  = (const float*)d_in[7];
    const float* ln2_b  = (const float*)d_in[8];
    const float* mlp_w1 = (const float*)d_in[9];
    const float* mlp_b1 = (const float*)d_in[10];
    const float* mlp_w2 = (const float*)d_in[11];
    const float* mlp_b2 = (const float*)d_in[12];
    const float* p_ln_g = (const float*)d_in[13];
    const float* p_ln_b = (const float*)d_in[14];
    const float* p_in_w = (const float*)d_in[15];
    const float* p_in_b = (const float*)d_in[16];
    const float* p_w1   = (const float*)d_in[17];
    const float* p_b1   = (const float*)d_in[18];
    const float* p_w2   = (const float*)d_in[19];
    const float* p_b2   = (const float*)d_in[20];
    const float* p_w3   = (const float*)d_in[21];
    const float* p_b3   = (const float*)d_in[22];

    float* X = (float*)d_out;   // residual stream lives in d_out

    float *XN, *QKV, *S, *AO, *MLP1, *PH, *PH2, *PCAT, *PH3, *PH4, *LOG, *GLOB, *PREV, *DFULL;
    cudaGetSymbolAddress((void**)&XN,   g_XN);
    cudaGetSymbolAddress((void**)&QKV,  g_QKV);
    cudaGetSymbolAddress((void**)&S,    g_S);
    cudaGetSymbolAddress((void**)&AO,   g_AO);
    cudaGetSymbolAddress((void**)&MLP1, g_MLP1);
    cudaGetSymbolAddress((void**)&PH,   g_PH);
    cudaGetSymbolAddress((void**)&PH2,  g_PH2);
    cudaGetSymbolAddress((void**)&PCAT, g_PCAT);
    cudaGetSymbolAddress((void**)&PH3,  g_PH3);
    cudaGetSymbolAddress((void**)&PH4,  g_PH4);
    cudaGetSymbolAddress((void**)&LOG,  g_LOG);
    cudaGetSymbolAddress((void**)&GLOB, g_GLOB);
    cudaGetSymbolAddress((void**)&PREV, g_PREV);
    cudaGetSymbolAddress((void**)&DFULL,g_DFULL);

    cudaMemcpyAsync(X, x_in, sizeof(float) * (size_t)NT * CC, cudaMemcpyDeviceToDevice);
    init_prev_kernel<<<(NPX + 255) / 256, 256>>>(PREV);

    int p = 0;
    int mask_active = 0;

    for (int i = 0; i < 12; i++) {
        if (i == 3 || i == 6 || i == 9) {
            // folded gumbel key for this stage (host-side threefry)
            unsigned fk0, fk1;
            tf2x32(0u, 42u, 0u, (unsigned)p, fk0, fk1);

            ln_kernel<<<NPX, 256>>>(X, p_ln_g + p * CC, p_ln_b + p * CC, PH, 1);
            sgemm<1, 0><<<dim3(CC / 64, NPX / 64), 256>>>(
                PH, p_in_w + (size_t)p * CC * CC, p_in_b + p * CC, nullptr, PH2, NPX, CC, CC);
            glob_kernel<<<BB, 256>>>(PH2, PREV, GLOB);
            concat_kernel<<<((size_t)NPX * CC + 255) / 256, 256>>>(PH2, GLOB, PCAT);
            sgemm<1, 0><<<dim3(384 / 64, NPX / 64), 256>>>(
                PCAT, p_w1 + (size_t)p * CC * 384, p_b1 + p * 384, nullptr, PH3, NPX, 384, CC);
            sgemm<1, 0><<<dim3(192 / 64, NPX / 64), 256>>>(
                PH3, p_w2 + (size_t)p * 384 * 192, p_b2 + p * 192, nullptr, PH4, NPX, 192, 384);
            logits_kernel<<<NPX / 8, 256>>>(PH4, p_w3 + (size_t)p * 192 * 2, p_b3 + p * 2, LOG);
            decision_kernel<<<(NPX + 255) / 256, 256>>>(LOG, PREV, DFULL, fk0, fk1);
            mask_active = 1;
            p++;
        }

        // attention block
        ln_kernel<<<NT, 256>>>(X, ln1_g + i * CC, ln1_b + i * CC, XN, 0);
        sgemm<0, 0><<<dim3(CQ / 64, (NT + 63) / 64), 256>>>(
            XN, qkv_w + (size_t)i * CC * CQ, qkv_b + i * CQ, nullptr, QKV, NT, CQ, CC);
        scores_kernel<<<dim3(7, 7, BB * HH), 256>>>(QKV, S);
        softmax_kernel<<<BB * HH * NN, 256>>>(S, DFULL, mask_active);
        av_kernel<<<((size_t)NT * CC + 255) / 256, 256>>>(S, QKV, AO);
        sgemm<0, 1><<<dim3(CC / 64, (NT + 63) / 64), 256>>>(
            AO, proj_w + (size_t)i * CC * CC, proj_b + i * CC, X, X, NT, CC, CC);

        // MLP block
        ln_kernel<<<NT, 256>>>(X, ln2_g + i * CC, ln2_b + i * CC, XN, 0);
        sgemm<1, 0><<<dim3(MM / 64, (NT + 63) / 64), 256>>>(
            XN, mlp_w1 + (size_t)i * CC * MM, mlp_b1 + i * MM, nullptr, MLP1, NT, MM, CC);
        sgemm<0, 1><<<dim3(CC / 64, (NT + 63) / 64), 256>>>(
            MLP1, mlp_w2 + (size_t)i * MM * CC, mlp_b2 + i * CC, X, X, NT, CC, MM);
    }
}

// round 8
// speedup vs baseline: 2.8230x; 2.8230x over previous
#include <cuda_runtime.h>
#include <cstdint>
#include <math.h>

// ---------------- problem constants ----------------
#define BB   64
#define NN   197
#define CC   768
#define HH   12
#define DHD  64
#define MM   3072
#define NT   (BB*NN)        // 12608 tokens
#define NPX  (BB*(NN-1))    // 12544 non-cls tokens
#define CQ   (3*CC)         // 2304

// ---------------- scratch (static device memory; no allocation) ----------------
__device__ float g_XN  [NT*CC];
__device__ float g_QKV [NT*CQ];
__device__ float g_S   [(size_t)BB*HH*NN*NN];
__device__ float g_AO  [NT*CC];
__device__ float g_MLP1[NT*MM];
__device__ float g_PH  [NPX*CC];
__device__ float g_PH2 [NPX*CC];
__device__ float g_PCAT[NPX*CC];
__device__ float g_PH3 [NPX*(CC/2)];
__device__ float g_PH4 [NPX*(CC/4)];
__device__ float g_LOG [NPX*2];
__device__ float g_GLOB[BB*(CC/2)];
__device__ float g_PREV[NPX];
__device__ float g_DFULL[BB*NN];

// ---------------- threefry-2x32 (matches JAX exactly) ----------------
__host__ __device__ __forceinline__ unsigned rotl32(unsigned v, int d) {
    return (v << d) | (v >> (32 - d));
}
__host__ __device__ __forceinline__ void tf2x32(unsigned k0, unsigned k1,
                                                unsigned x0, unsigned x1,
                                                unsigned& o0, unsigned& o1) {
    unsigned ks2 = k0 ^ k1 ^ 0x1BD11BDAu;
    x0 += k0; x1 += k1;
#define TF_RND(r) { x0 += x1; x1 = rotl32(x1, r); x1 ^= x0; }
    TF_RND(13) TF_RND(15) TF_RND(26) TF_RND(6)   x0 += k1;  x1 += ks2 + 1u;
    TF_RND(17) TF_RND(29) TF_RND(16) TF_RND(24)  x0 += ks2; x1 += k0  + 2u;
    TF_RND(13) TF_RND(15) TF_RND(26) TF_RND(6)   x0 += k0;  x1 += k1  + 3u;
    TF_RND(17) TF_RND(29) TF_RND(16) TF_RND(24)  x0 += k1;  x1 += ks2 + 4u;
    TF_RND(13) TF_RND(15) TF_RND(26) TF_RND(6)   x0 += ks2; x1 += k0  + 5u;
#undef TF_RND
    o0 = x0; o1 = x1;
}

// JAX partitionable threefry: bits = bits1 ^ bits2 for 32-bit output.
__device__ __forceinline__ float jax_uniform_elem(unsigned k0, unsigned k1, unsigned e) {
    unsigned o0, o1;
    tf2x32(k0, k1, 0u, e, o0, o1);
    unsigned bits = o0 ^ o1;
    unsigned u = (bits >> 9) | 0x3f800000u;
    float f = __uint_as_float(u) - 1.0f;       // [0,1)
    return fmaxf(1e-10f, __fadd_rn(f, 1e-10f));
}

// ---------------- helpers ----------------
__device__ __forceinline__ float block_sum256(float v, float* red) {
    int tid = threadIdx.x;
    red[tid] = v; __syncthreads();
    #pragma unroll
    for (int s = 128; s > 0; s >>= 1) {
        if (tid < s) red[tid] += red[tid + s];
        __syncthreads();
    }
    float r = red[0]; __syncthreads();
    return r;
}
__device__ __forceinline__ float block_max256(float v, float* red) {
    int tid = threadIdx.x;
    red[tid] = v; __syncthreads();
    #pragma unroll
    for (int s = 128; s > 0; s >>= 1) {
        if (tid < s) red[tid] = fmaxf(red[tid], red[tid + s]);
        __syncthreads();
    }
    float r = red[0]; __syncthreads();
    return r;
}
__device__ __forceinline__ float gelu_exact(float v) {
    return 0.5f * v * (1.0f + erff(v * 0.70710678118654752440f));
}
__device__ __forceinline__ unsigned f2tf32(float x) {
    unsigned r;
    asm("cvt.rna.tf32.f32 %0, %1;" : "=r"(r) : "f"(x));
    return r;
}
__device__ __forceinline__ void mma_tf32(float* d, const unsigned* a, const unsigned* b) {
    asm volatile(
        "mma.sync.aligned.m16n8k8.row.col.f32.tf32.tf32.f32 "
        "{%0,%1,%2,%3}, {%4,%5,%6,%7}, {%8,%9}, {%0,%1,%2,%3};"
        : "+f"(d[0]), "+f"(d[1]), "+f"(d[2]), "+f"(d[3])
        : "r"(a[0]), "r"(a[1]), "r"(a[2]), "r"(a[3]), "r"(b[0]), "r"(b[1]));
}

// ---------------- TF32 tensor-core GEMM ----------------
// out[M,N] = A[M,K] @ W[K,N] + bias ; ACT -> GELU ; RES -> += res
// BM=128, BN=64, BK=32, 256 threads (8 warps, 4x2), warp tile 32x32.
// smem: As[128][36], Bs[32][72], double buffered (55296 bytes dynamic).
#define TG_STAGE   6912   // floats per stage (4608 + 2304)
#define TG_SMEMB   (2 * TG_STAGE * 4)

template<int ACT, int RES>
__global__ void __launch_bounds__(256, 2) tgemm(
    const float* __restrict__ A, const float* __restrict__ W,
    const float* __restrict__ bias, const float* __restrict__ res,
    float* __restrict__ out, int M, int N, int K) {
    extern __shared__ float smem[];
    int tid = threadIdx.x;
    int warp = tid >> 5, lane = tid & 31;
    int g = lane >> 2, tig = lane & 3;
    int wm = warp >> 1, wn = warp & 1;
    int WR = wm * 32, WC = wn * 32;
    int row0 = blockIdx.y * 128, col0 = blockIdx.x * 64;

    float acc[2][4][4] = {};
    int nk = K >> 5;

    // async tile loader
    auto load_tile = [&](int stage, int k0) {
        float* As = smem + stage * TG_STAGE;
        float* Bs = As + 4608;
        #pragma unroll
        for (int s = 0; s < 4; s++) {
            int f = tid + s * 256;
            int row = f >> 3, c4 = (f & 7) * 4;
            unsigned dst = (unsigned)__cvta_generic_to_shared(As + row * 36 + c4);
            const float* src = A + (size_t)(row0 + row) * K + k0 + c4;
            int sz = (row0 + row < M) ? 16 : 0;
            asm volatile("cp.async.cg.shared.global [%0], [%1], 16, %2;"
                         :: "r"(dst), "l"(src), "r"(sz));
        }
        #pragma unroll
        for (int s = 0; s < 2; s++) {
            int f = tid + s * 256;
            int row = f >> 4, c4 = (f & 15) * 4;
            unsigned dst = (unsigned)__cvta_generic_to_shared(Bs + row * 72 + c4);
            const float* src = W + (size_t)(k0 + row) * N + col0 + c4;
            asm volatile("cp.async.cg.shared.global [%0], [%1], 16;"
                         :: "r"(dst), "l"(src));
        }
        asm volatile("cp.async.commit_group;");
    };

    load_tile(0, 0);

    for (int kt = 0; kt < nk; kt++) {
        asm volatile("cp.async.wait_group 0;");
        __syncthreads();
        const float* Ac = smem + (kt & 1) * TG_STAGE;
        const float* Bc = Ac + 4608;
        if (kt + 1 < nk) load_tile((kt + 1) & 1, (kt + 1) << 5);

        #pragma unroll
        for (int kk = 0; kk < 32; kk += 8) {
            unsigned af[2][4], bf[4][2];
            #pragma unroll
            for (int i = 0; i < 2; i++) {
                int ar = WR + i * 16 + g;
                af[i][0] = f2tf32(Ac[ar * 36 + kk + tig]);
                af[i][1] = f2tf32(Ac[(ar + 8) * 36 + kk + tig]);
                af[i][2] = f2tf32(Ac[ar * 36 + kk + tig + 4]);
                af[i][3] = f2tf32(Ac[(ar + 8) * 36 + kk + tig + 4]);
            }
            #pragma unroll
            for (int j = 0; j < 4; j++) {
                int bc = WC + j * 8 + g;
                bf[j][0] = f2tf32(Bc[(kk + tig) * 72 + bc]);
                bf[j][1] = f2tf32(Bc[(kk + tig + 4) * 72 + bc]);
            }
            #pragma unroll
            for (int i = 0; i < 2; i++)
                #pragma unroll
                for (int j = 0; j < 4; j++)
                    mma_tf32(acc[i][j], af[i], bf[j]);
        }
        __syncthreads();
    }

    // epilogue
    #pragma unroll
    for (int i = 0; i < 2; i++) {
        #pragma unroll
        for (int j = 0; j < 4; j++) {
            int r = row0 + WR + i * 16 + g;
            int c = col0 + WC + j * 8 + 2 * tig;
            float b0 = bias[c], b1 = bias[c + 1];
            if (r < M) {
                float v0 = acc[i][j][0] + b0;
                float v1 = acc[i][j][1] + b1;
                if (ACT) { v0 = gelu_exact(v0); v1 = gelu_exact(v1); }
                if (RES) { v0 += res[(size_t)r * N + c]; v1 += res[(size_t)r * N + c + 1]; }
                out[(size_t)r * N + c]     = v0;
                out[(size_t)r * N + c + 1] = v1;
            }
            int r2 = r + 8;
            if (r2 < M) {
                float v2 = acc[i][j][2] + b0;
                float v3 = acc[i][j][3] + b1;
                if (ACT) { v2 = gelu_exact(v2); v3 = gelu_exact(v3); }
                if (RES) { v2 += res[(size_t)r2 * N + c]; v3 += res[(size_t)r2 * N + c + 1]; }
                out[(size_t)r2 * N + c]     = v2;
                out[(size_t)r2 * N + c + 1] = v3;
            }
        }
    }
}

// ---------------- kernels ----------------
__global__ void init_prev_kernel(float* prev) {
    int t = blockIdx.x * blockDim.x + threadIdx.x;
    if (t < NPX) prev[t] = 1.0f;
}

// LayerNorm over C=768. 256 threads/block, 3 elems/thread. mode 1: skip cls rows.
__global__ void ln_kernel(const float* __restrict__ in, const float* __restrict__ g,
                          const float* __restrict__ bta, float* __restrict__ out, int mode) {
    int r = blockIdx.x;
    int ir = r;
    if (mode == 1) { int b = r / 196, j = r % 196; ir = b * NN + 1 + j; }
    const float* x = in + (size_t)ir * CC;
    int tid = threadIdx.x;
    __shared__ float red[256];
    float v0 = x[tid], v1 = x[tid + 256], v2 = x[tid + 512];
    float total = block_sum256(v0 + v1 + v2, red);
    float mu = total * (1.0f / CC);
    float d0 = v0 - mu, d1 = v1 - mu, d2 = v2 - mu;
    float tot2 = block_sum256(d0*d0 + d1*d1 + d2*d2, red);
    float rstd = rsqrtf(tot2 * (1.0f / CC) + 1e-5f);
    float* o = out + (size_t)r * CC;
    o[tid]       = d0 * rstd * g[tid]       + bta[tid];
    o[tid + 256] = d1 * rstd * g[tid + 256] + bta[tid + 256];
    o[tid + 512] = d2 * rstd * g[tid + 512] + bta[tid + 512];
}

// scores: S[b,h,q,k] = q_vec . k_vec  (raw dot; scale+mask in softmax)
__global__ void scores_kernel(const float* __restrict__ qkv, float* __restrict__ S) {
    int bh = blockIdx.z; int b = bh / HH, h = bh % HH;
    int q0 = blockIdx.x * 32, k0 = blockIdx.y * 32;
    __shared__ float Qs[32][17];
    __shared__ float Ks[32][17];
    int tid = threadIdx.x;
    int tx = tid & 15, ty = tid >> 4;
    float acc[2][2] = {};
    for (int d0 = 0; d0 < DHD; d0 += 16) {
        #pragma unroll
        for (int i = 0; i < 2; i++) {
            int idx = tid + i * 256;
            int ri = idx >> 4, dd = idx & 15;
            int q = q0 + ri;
            Qs[ri][dd] = (q < NN) ? qkv[(size_t)(b * NN + q) * CQ + h * DHD + d0 + dd] : 0.0f;
            int k = k0 + ri;
            Ks[ri][dd] = (k < NN) ? qkv[(size_t)(b * NN + k) * CQ + CC + h * DHD + d0 + dd] : 0.0f;
        }
        __syncthreads();
        #pragma unroll
        for (int dd = 0; dd < 16; dd++) {
            float qa0 = Qs[ty * 2][dd],     qa1 = Qs[ty * 2 + 1][dd];
            float kb0 = Ks[tx * 2][dd],     kb1 = Ks[tx * 2 + 1][dd];
            acc[0][0] = fmaf(qa0, kb0, acc[0][0]);
            acc[0][1] = fmaf(qa0, kb1, acc[0][1]);
            acc[1][0] = fmaf(qa1, kb0, acc[1][0]);
            acc[1][1] = fmaf(qa1, kb1, acc[1][1]);
        }
        __syncthreads();
    }
    #pragma unroll
    for (int i = 0; i < 2; i++) {
        int q = q0 + ty * 2 + i;
        if (q >= NN) continue;
        #pragma unroll
        for (int j = 0; j < 2; j++) {
            int k = k0 + tx * 2 + j;
            if (k >= NN) continue;
            S[(((size_t)bh * NN) + q) * NN + k] = acc[i][j];
        }
    }
}

// softmax over k with scale 0.125 and drop-mask (exact -1e9 like reference)
__global__ void softmax_kernel(float* __restrict__ S, const float* __restrict__ dfull,
                               int mask_active) {
    int rid = blockIdx.x;                 // (b*H+h)*N + q
    int q = rid % NN; int bh = rid / NN; int b = bh / HH;
    float* row = S + (size_t)rid * NN;
    int tid = threadIdx.x;
    __shared__ float red[256];
    float dq = mask_active ? dfull[b * NN + q] : 1.0f;
    float val = -3.0e38f;
    if (tid < NN) {
        float raw = row[tid] * 0.125f;
        bool keep = true;
        if (mask_active) keep = (tid == q) || (dq > 0.0f && dfull[b * NN + tid] > 0.0f);
        val = keep ? raw : -1e9f;
    }
    float m = block_max256(val, red);
    float e = (tid < NN) ? expf(val - m) : 0.0f;
    float s = block_sum256(e, red);
    if (tid < NN) row[tid] = e / s;
}

// attn @ V : AO[b,q,h*64+d] = sum_k P[b,h,q,k] * V[b,k,h*64+d]
__global__ void av_kernel(const float* __restrict__ P, const float* __restrict__ qkv,
                          float* __restrict__ AO) {
    size_t t = (size_t)blockIdx.x * blockDim.x + threadIdx.x;
    if (t >= (size_t)NT * CC) return;
    int col = (int)(t % CC); int rowt = (int)(t / CC);
    int b = rowt / NN, q = rowt % NN;
    int h = col / DHD;
    const float* prow = P + ((size_t)(b * HH + h) * NN + q) * NN;
    const float* vcol = qkv + (size_t)(b * NN) * CQ + 2 * CC + col;
    float acc = 0.0f;
    for (int k = 0; k < NN; k++) acc = fmaf(prow[k], vcol[(size_t)k * CQ], acc);
    AO[(size_t)rowt * CC + col] = acc;
}

// predictor: glob[b,c] = sum_j h2[b,j,384+c]*prev[b,j] / (sum_j prev[b,j] + 1e-20)
__global__ void glob_kernel(const float* __restrict__ ph2, const float* __restrict__ prev,
                            float* __restrict__ glob) {
    int b = blockIdx.x;
    int tid = threadIdx.x;
    __shared__ float red[256];
    float pv = (tid < 196) ? prev[b * 196 + tid] : 0.0f;
    float psum = block_sum256(pv, red);
    float denom = psum + 1e-20f;
    for (int c = tid; c < 384; c += 256) {
        float acc = 0.0f;
        for (int j = 0; j < 196; j++)
            acc = fmaf(ph2[((size_t)(b * 196 + j)) * CC + 384 + c], prev[b * 196 + j], acc);
        glob[b * 384 + c] = acc / denom;
    }
}

__global__ void concat_kernel(const float* __restrict__ ph2, const float* __restrict__ glob,
                              float* __restrict__ pcat) {
    size_t t = (size_t)blockIdx.x * blockDim.x + threadIdx.x;
    if (t >= (size_t)NPX * CC) return;
    int c = (int)(t % CC); int row = (int)(t / CC); int b = row / 196;
    pcat[t] = (c < 384) ? ph2[(size_t)row * CC + c] : glob[b * 384 + (c - 384)];
}

// logits: one warp per token; PH4[t,0:192] @ w3[192,2] + b3
__global__ void logits_kernel(const float* __restrict__ ph4, const float* __restrict__ w,
                              const float* __restrict__ bias, float* __restrict__ out) {
    int warp = (blockIdx.x * blockDim.x + threadIdx.x) >> 5;
    int lane = threadIdx.x & 31;
    if (warp >= NPX) return;
    const float* row = ph4 + (size_t)warp * 192;
    float a0 = 0.0f, a1 = 0.0f;
    for (int c = lane; c < 192; c += 32) {
        float h = row[c];
        a0 = fmaf(h, w[c * 2], a0);
        a1 = fmaf(h, w[c * 2 + 1], a1);
    }
    #pragma unroll
    for (int o = 16; o > 0; o >>= 1) {
        a0 += __shfl_down_sync(0xffffffffu, a0, o);
        a1 += __shfl_down_sync(0xffffffffu, a1, o);
    }
    if (lane == 0) {
        out[warp * 2]     = a0 + bias[0];
        out[warp * 2 + 1] = a1 + bias[1];
    }
}

// gumbel decision: updates prev + dfull
__global__ void decision_kernel(const float* __restrict__ logits, float* __restrict__ prev,
                                float* __restrict__ dfull, unsigned k0, unsigned k1) {
    int t = blockIdx.x * blockDim.x + threadIdx.x;
    if (t >= NPX) return;
    int b = t / 196, j = t % 196;
    float l0 = logits[t * 2], l1 = logits[t * 2 + 1];
    float m = fmaxf(l0, l1);
    float e0 = expf(l0 - m), e1 = expf(l1 - m);
    float inv = 1.0f / (e0 + e1);
    float s0 = e0 * inv, s1 = e1 * inv;
    float u0 = jax_uniform_elem(k0, k1, (unsigned)(2 * t));
    float u1 = jax_uniform_elem(k0, k1, (unsigned)(2 * t + 1));
    float g0 = -logf(-logf(u0));
    float g1 = -logf(-logf(u1));
    float a0 = s0 + g0, a1 = s1 + g1;
    float hard1 = (a1 > a0) ? 1.0f : 0.0f;
    float m2 = fmaxf(a0, a1);
    float y0e = expf(a0 - m2), y1e = expf(a1 - m2);
    float ys1 = y1e / (y0e + y1e);
    float y1 = (hard1 + ys1) - ys1;   // straight-through forward value
    float dec = y1 * prev[t];
    prev[t] = dec;
    dfull[b * NN + 1 + j] = dec;
    if (j == 0) dfull[b * NN] = 1.0f;
}

// ---------------- host orchestration ----------------
extern "C" void kernel_launch(void* const* d_in, const int* in_sizes, int n_in,
                              void* d_out, int out_size) {
    const float* x_in   = (const float*)d_in[0];
    const float* ln1_g  = (const float*)d_in[1];
    const float* ln1_b  = (const float*)d_in[2];
    const float* qkv_w  = (const float*)d_in[3];
    const float* qkv_b  = (const float*)d_in[4];
    const float* proj_w = (const float*)d_in[5];
    const float* proj_b = (const float*)d_in[6];
    const float* ln2_g  = (const float*)d_in[7];
    const float* ln2_b  = (const float*)d_in[8];
    const float* mlp_w1 = (const float*)d_in[9];
    const float* mlp_b1 = (const float*)d_in[10];
    const float* mlp_w2 = (const float*)d_in[11];
    const float* mlp_b2 = (const float*)d_in[12];
    const float* p_ln_g = (const float*)d_in[13];
    const float* p_ln_b = (const float*)d_in[14];
    const float* p_in_w = (const float*)d_in[15];
    const float* p_in_b = (const float*)d_in[16];
    const float* p_w1   = (const float*)d_in[17];
    const float* p_b1   = (const float*)d_in[18];
    const float* p_w2   = (const float*)d_in[19];
    const float* p_b2   = (const float*)d_in[20];
    const float* p_w3   = (const float*)d_in[21];
    const float* p_b3   = (const float*)d_in[22];

    float* X = (float*)d_out;   // residual stream lives in d_out

    float *XN, *QKV, *S, *AO, *MLP1, *PH, *PH2, *PCAT, *PH3, *PH4, *LOG, *GLOB, *PREV, *DFULL;
    cudaGetSymbolAddress((void**)&XN,   g_XN);
    cudaGetSymbolAddress((void**)&QKV,  g_QKV);
    cudaGetSymbolAddress((void**)&S,    g_S);
    cudaGetSymbolAddress((void**)&AO,   g_AO);
    cudaGetSymbolAddress((void**)&MLP1, g_MLP1);
    cudaGetSymbolAddress((void**)&PH,   g_PH);
    cudaGetSymbolAddress((void**)&PH2,  g_PH2);
    cudaGetSymbolAddress((void**)&PCAT, g_PCAT);
    cudaGetSymbolAddress((void**)&PH3,  g_PH3);
    cudaGetSymbolAddress((void**)&PH4,  g_PH4);
    cudaGetSymbolAddress((void**)&LOG,  g_LOG);
    cudaGetSymbolAddress((void**)&GLOB, g_GLOB);
    cudaGetSymbolAddress((void**)&PREV, g_PREV);
    cudaGetSymbolAddress((void**)&DFULL,g_DFULL);

    cudaFuncSetAttribute(tgemm<0,0>, cudaFuncAttributeMaxDynamicSharedMemorySize, TG_SMEMB);
    cudaFuncSetAttribute(tgemm<1,0>, cudaFuncAttributeMaxDynamicSharedMemorySize, TG_SMEMB);
    cudaFuncSetAttribute(tgemm<0,1>, cudaFuncAttributeMaxDynamicSharedMemorySize, TG_SMEMB);

    cudaMemcpyAsync(X, x_in, sizeof(float) * (size_t)NT * CC, cudaMemcpyDeviceToDevice);
    init_prev_kernel<<<(NPX + 255) / 256, 256>>>(PREV);

    int p = 0;
    int mask_active = 0;

    for (int i = 0; i < 12; i++) {
        if (i == 3 || i == 6 || i == 9) {
            unsigned fk0, fk1;
            tf2x32(0u, 42u, 0u, (unsigned)p, fk0, fk1);

            ln_kernel<<<NPX, 256>>>(X, p_ln_g + p * CC, p_ln_b + p * CC, PH, 1);
            tgemm<1, 0><<<dim3(CC / 64, (NPX + 127) / 128), 256, TG_SMEMB>>>(
                PH, p_in_w + (size_t)p * CC * CC, p_in_b + p * CC, nullptr, PH2, NPX, CC, CC);
            glob_kernel<<<BB, 256>>>(PH2, PREV, GLOB);
            concat_kernel<<<((size_t)NPX * CC + 255) / 256, 256>>>(PH2, GLOB, PCAT);
            tgemm<1, 0><<<dim3(384 / 64, (NPX + 127) / 128), 256, TG_SMEMB>>>(
                PCAT, p_w1 + (size_t)p * CC * 384, p_b1 + p * 384, nullptr, PH3, NPX, 384, CC);
            tgemm<1, 0><<<dim3(192 / 64, (NPX + 127) / 128), 256, TG_SMEMB>>>(
                PH3, p_w2 + (size_t)p * 384 * 192, p_b2 + p * 192, nullptr, PH4, NPX, 192, 384);
            logits_kernel<<<NPX / 8, 256>>>(PH4, p_w3 + (size_t)p * 192 * 2, p_b3 + p * 2, LOG);
            decision_kernel<<<(NPX + 255) / 256, 256>>>(LOG, PREV, DFULL, fk0, fk1);
            mask_active = 1;
            p++;
        }

        // attention block
        ln_kernel<<<NT, 256>>>(X, ln1_g + i * CC, ln1_b + i * CC, XN, 0);
        tgemm<0, 0><<<dim3(CQ / 64, (NT + 127) / 128), 256, TG_SMEMB>>>(
            XN, qkv_w + (size_t)i * CC * CQ, qkv_b + i * CQ, nullptr, QKV, NT, CQ, CC);
        scores_kernel<<<dim3(7, 7, BB * HH), 256>>>(QKV, S);
        softmax_kernel<<<BB * HH * NN, 256>>>(S, DFULL, mask_active);
        av_kernel<<<((size_t)NT * CC + 255) / 256, 256>>>(S, QKV, AO);
        tgemm<0, 1><<<dim3(CC / 64, (NT + 127) / 128), 256, TG_SMEMB>>>(
            AO, proj_w + (size_t)i * CC * CC, proj_b + i * CC, X, X, NT, CC, CC);

        // MLP block
        ln_kernel<<<NT, 256>>>(X, ln2_g + i * CC, ln2_b + i * CC, XN, 0);
        tgemm<1, 0><<<dim3(MM / 64, (NT + 127) / 128), 256, TG_SMEMB>>>(
            XN, mlp_w1 + (size_t)i * CC * MM, mlp_b1 + i * MM, nullptr, MLP1, NT, MM, CC);
        tgemm<0, 1><<<dim3(CC / 64, (NT + 127) / 128), 256, TG_SMEMB>>>(
            MLP1, mlp_w2 + (size_t)i * MM * CC, mlp_b2 + i * CC, X, X, NT, CC, MM);
    }
}

// round 10
// speedup vs baseline: 3.9194x; 1.3884x over previous
#include <cuda_runtime.h>
#include <cstdint>
#include <math.h>

// ---------------- problem constants ----------------
#define BB   64
#define NN   197
#define CC   768
#define HH   12
#define DHD  64
#define MM   3072
#define NT   (BB*NN)        // 12608 tokens
#define NPX  (BB*(NN-1))    // 12544 non-cls tokens
#define CQ   (3*CC)         // 2304

// ---------------- scratch (static device memory; no allocation) ----------------
__device__ float g_XN  [NT*CC];
__device__ float g_QKV [NT*CQ];
__device__ float g_AO  [NT*CC];
__device__ float g_MLP1[NT*MM];
__device__ float g_PH  [NPX*CC];
__device__ float g_PH2 [NPX*CC];
__device__ float g_PCAT[NPX*CC];
__device__ float g_PH3 [NPX*(CC/2)];
__device__ float g_PH4 [NPX*(CC/4)];
__device__ float g_LOG [NPX*2];
__device__ float g_GLOB[BB*(CC/2)];
__device__ float g_PREV[NPX];
__device__ float g_DFULL[BB*NN];

// ---------------- threefry-2x32 (matches JAX exactly) ----------------
__host__ __device__ __forceinline__ unsigned rotl32(unsigned v, int d) {
    return (v << d) | (v >> (32 - d));
}
__host__ __device__ __forceinline__ void tf2x32(unsigned k0, unsigned k1,
                                                unsigned x0, unsigned x1,
                                                unsigned& o0, unsigned& o1) {
    unsigned ks2 = k0 ^ k1 ^ 0x1BD11BDAu;
    x0 += k0; x1 += k1;
#define TF_RND(r) { x0 += x1; x1 = rotl32(x1, r); x1 ^= x0; }
    TF_RND(13) TF_RND(15) TF_RND(26) TF_RND(6)   x0 += k1;  x1 += ks2 + 1u;
    TF_RND(17) TF_RND(29) TF_RND(16) TF_RND(24)  x0 += ks2; x1 += k0  + 2u;
    TF_RND(13) TF_RND(15) TF_RND(26) TF_RND(6)   x0 += k0;  x1 += k1  + 3u;
    TF_RND(17) TF_RND(29) TF_RND(16) TF_RND(24)  x0 += k1;  x1 += ks2 + 4u;
    TF_RND(13) TF_RND(15) TF_RND(26) TF_RND(6)   x0 += ks2; x1 += k0  + 5u;
#undef TF_RND
    o0 = x0; o1 = x1;
}

// JAX partitionable threefry: bits = bits1 ^ bits2 for 32-bit output.
__device__ __forceinline__ float jax_uniform_elem(unsigned k0, unsigned k1, unsigned e) {
    unsigned o0, o1;
    tf2x32(k0, k1, 0u, e, o0, o1);
    unsigned bits = o0 ^ o1;
    unsigned u = (bits >> 9) | 0x3f800000u;
    float f = __uint_as_float(u) - 1.0f;       // [0,1)
    return fmaxf(1e-10f, __fadd_rn(f, 1e-10f));
}

// ---------------- helpers ----------------
__device__ __forceinline__ float block_sum256(float v, float* red) {
    int tid = threadIdx.x;
    red[tid] = v; __syncthreads();
    #pragma unroll
    for (int s = 128; s > 0; s >>= 1) {
        if (tid < s) red[tid] += red[tid + s];
        __syncthreads();
    }
    float r = red[0]; __syncthreads();
    return r;
}
__device__ __forceinline__ float gelu_exact(float v) {
    return 0.5f * v * (1.0f + erff(v * 0.70710678118654752440f));
}
__device__ __forceinline__ unsigned f2tf32(float x) {
    unsigned r;
    asm("cvt.rna.tf32.f32 %0, %1;" : "=r"(r) : "f"(x));
    return r;
}
__device__ __forceinline__ void mma_tf32(float* d, const unsigned* a, const unsigned* b) {
    asm volatile(
        "mma.sync.aligned.m16n8k8.row.col.f32.tf32.tf32.f32 "
        "{%0,%1,%2,%3}, {%4,%5,%6,%7}, {%8,%9}, {%0,%1,%2,%3};"
        : "+f"(d[0]), "+f"(d[1]), "+f"(d[2]), "+f"(d[3])
        : "r"(a[0]), "r"(a[1]), "r"(a[2]), "r"(a[3]), "r"(b[0]), "r"(b[1]));
}

// ---------------- TF32 tensor-core GEMM ----------------
#define TG_STAGE   6912   // floats per stage (4608 + 2304)
#define TG_SMEMB   (2 * TG_STAGE * 4)

template<int ACT, int RES>
__global__ void __launch_bounds__(256, 2) tgemm(
    const float* __restrict__ A, const float* __restrict__ W,
    const float* __restrict__ bias, const float* __restrict__ res,
    float* __restrict__ out, int M, int N, int K) {
    extern __shared__ float smem[];
    int tid = threadIdx.x;
    int warp = tid >> 5, lane = tid & 31;
    int g = lane >> 2, tig = lane & 3;
    int wm = warp >> 1, wn = warp & 1;
    int WR = wm * 32, WC = wn * 32;
    int row0 = blockIdx.y * 128, col0 = blockIdx.x * 64;

    float acc[2][4][4] = {};
    int nk = K >> 5;

    auto load_tile = [&](int stage, int k0) {
        float* As = smem + stage * TG_STAGE;
        float* Bs = As + 4608;
        #pragma unroll
        for (int s = 0; s < 4; s++) {
            int f = tid + s * 256;
            int row = f >> 3, c4 = (f & 7) * 4;
            unsigned dst = (unsigned)__cvta_generic_to_shared(As + row * 36 + c4);
            const float* src = A + (size_t)(row0 + row) * K + k0 + c4;
            int sz = (row0 + row < M) ? 16 : 0;
            asm volatile("cp.async.cg.shared.global [%0], [%1], 16, %2;"
                         :: "r"(dst), "l"(src), "r"(sz));
        }
        #pragma unroll
        for (int s = 0; s < 2; s++) {
            int f = tid + s * 256;
            int row = f >> 4, c4 = (f & 15) * 4;
            unsigned dst = (unsigned)__cvta_generic_to_shared(Bs + row * 72 + c4);
            const float* src = W + (size_t)(k0 + row) * N + col0 + c4;
            asm volatile("cp.async.cg.shared.global [%0], [%1], 16;"
                         :: "r"(dst), "l"(src));
        }
        asm volatile("cp.async.commit_group;");
    };

    load_tile(0, 0);

    for (int kt = 0; kt < nk; kt++) {
        asm volatile("cp.async.wait_group 0;");
        __syncthreads();
        const float* Ac = smem + (kt & 1) * TG_STAGE;
        const float* Bc = Ac + 4608;
        if (kt + 1 < nk) load_tile((kt + 1) & 1, (kt + 1) << 5);

        #pragma unroll
        for (int kk = 0; kk < 32; kk += 8) {
            unsigned af[2][4], bf[4][2];
            #pragma unroll
            for (int i = 0; i < 2; i++) {
                int ar = WR + i * 16 + g;
                af[i][0] = f2tf32(Ac[ar * 36 + kk + tig]);
                af[i][1] = f2tf32(Ac[(ar + 8) * 36 + kk + tig]);
                af[i][2] = f2tf32(Ac[ar * 36 + kk + tig + 4]);
                af[i][3] = f2tf32(Ac[(ar + 8) * 36 + kk + tig + 4]);
            }
            #pragma unroll
            for (int j = 0; j < 4; j++) {
                int bc = WC + j * 8 + g;
                bf[j][0] = f2tf32(Bc[(kk + tig) * 72 + bc]);
                bf[j][1] = f2tf32(Bc[(kk + tig + 4) * 72 + bc]);
            }
            #pragma unroll
            for (int i = 0; i < 2; i++)
                #pragma unroll
                for (int j = 0; j < 4; j++)
                    mma_tf32(acc[i][j], af[i], bf[j]);
        }
        __syncthreads();
    }

    #pragma unroll
    for (int i = 0; i < 2; i++) {
        #pragma unroll
        for (int j = 0; j < 4; j++) {
            int r = row0 + WR + i * 16 + g;
            int c = col0 + WC + j * 8 + 2 * tig;
            float b0 = bias[c], b1 = bias[c + 1];
            if (r < M) {
                float v0 = acc[i][j][0] + b0;
                float v1 = acc[i][j][1] + b1;
                if (ACT) { v0 = gelu_exact(v0); v1 = gelu_exact(v1); }
                if (RES) { v0 += res[(size_t)r * N + c]; v1 += res[(size_t)r * N + c + 1]; }
                out[(size_t)r * N + c]     = v0;
                out[(size_t)r * N + c + 1] = v1;
            }
            int r2 = r + 8;
            if (r2 < M) {
                float v2 = acc[i][j][2] + b0;
                float v3 = acc[i][j][3] + b1;
                if (ACT) { v2 = gelu_exact(v2); v3 = gelu_exact(v3); }
                if (RES) { v2 += res[(size_t)r2 * N + c]; v3 += res[(size_t)r2 * N + c + 1]; }
                out[(size_t)r2 * N + c]     = v2;
                out[(size_t)r2 * N + c + 1] = v3;
            }
        }
    }
}

// ---------------- fused attention (3xTF32 mma) ----------------
// One block per (qtile=64 rows, head, batch). Full K range in smem.
#define ANP    224          // padded key length (28 * 8)
#define QK_STR 68           // ≡4 mod 32: A-frag & colmajor-B-frag conflict-free
#define V_STR  72           // ≡8 mod 32: rowmajor-B-frag conflict-free
#define S_STR  228          // ≡4 mod 32: A-frag conflict-free
#define QS_OFF 0
#define KS_OFF 4352
#define VS_OFF 19584
#define SS_OFF 35712
#define D_OFF  50304
#define ATT_SMEMB (50528 * 4)

__global__ void __launch_bounds__(256, 1) attn_kernel(
    const float* __restrict__ qkv, const float* __restrict__ dfull,
    float* __restrict__ AO, int mask_active) {
    extern __shared__ float sm[];
    float* Qs = sm + QS_OFF;   // [64][68]
    float* Ks = sm + KS_OFF;   // [224][68]  (token-major, d contiguous)
    float* Vs = sm + VS_OFF;   // [224][72]
    float* Ss = sm + SS_OFF;   // [64][228]
    float* Dm = sm + D_OFF;    // [224]

    int qt = blockIdx.x, h = blockIdx.y, b = blockIdx.z;
    int q0 = qt * 64;
    int tid = threadIdx.x, warp = tid >> 5, lane = tid & 31;
    int g = lane >> 2, tig = lane & 3;

    // ---- load tiles (coalesced; zero padding) ----
    #pragma unroll
    for (int it = 0; it < 16; it++) {
        int idx = tid + it * 256; int r = idx >> 6, d = idx & 63;
        int q = q0 + r;
        Qs[r * QK_STR + d] = (q < NN) ? qkv[(size_t)(b * NN + q) * CQ + h * DHD + d] : 0.0f;
    }
    #pragma unroll
    for (int it = 0; it < 56; it++) {
        int idx = tid + it * 256; int r = idx >> 6, d = idx & 63;
        bool v = (r < NN);
        Ks[r * QK_STR + d] = v ? qkv[(size_t)(b * NN + r) * CQ + CC     + h * DHD + d] : 0.0f;
        Vs[r * V_STR  + d] = v ? qkv[(size_t)(b * NN + r) * CQ + 2 * CC + h * DHD + d] : 0.0f;
    }
    if (tid < ANP) Dm[tid] = (mask_active && tid < NN) ? dfull[b * NN + tid] : 1.0f;
    __syncthreads();

    // ---- S = Q K^T (3xTF32). warps: 2 (rows of 32) x 4 (cols of 56) ----
    {
        int wm = warp >> 2, wn = warp & 3;
        float acc[2][7][4] = {};
        #pragma unroll
        for (int kk = 0; kk < DHD; kk += 8) {
            unsigned ah[2][4], al[2][4];
            #pragma unroll
            for (int i = 0; i < 2; i++) {
                int ar = wm * 32 + i * 16 + g;
                #pragma unroll
                for (int v = 0; v < 4; v++) {
                    int rr = ar + ((v & 1) ? 8 : 0);
                    int cc = kk + tig + ((v >> 1) ? 4 : 0);
                    float x = Qs[rr * QK_STR + cc];
                    unsigned hb = f2tf32(x);
                    ah[i][v] = hb;
                    al[i][v] = f2tf32(x - __uint_as_float(hb));
                }
            }
            unsigned bh[7][2], bl[7][2];
            #pragma unroll
            for (int j = 0; j < 7; j++) {
                int n = wn * 56 + j * 8 + g;
                #pragma unroll
                for (int v = 0; v < 2; v++) {
                    float x = Ks[n * QK_STR + kk + tig + (v ? 4 : 0)];
                    unsigned hb = f2tf32(x);
                    bh[j][v] = hb;
                    bl[j][v] = f2tf32(x - __uint_as_float(hb));
                }
            }
            #pragma unroll
            for (int i = 0; i < 2; i++)
                #pragma unroll
                for (int j = 0; j < 7; j++) {
                    mma_tf32(acc[i][j], ah[i], bh[j]);
                    mma_tf32(acc[i][j], ah[i], bl[j]);
                    mma_tf32(acc[i][j], al[i], bh[j]);
                }
        }
        #pragma unroll
        for (int i = 0; i < 2; i++)
            #pragma unroll
            for (int j = 0; j < 7; j++) {
                int r = wm * 32 + i * 16 + g;
                int c = wn * 56 + j * 8 + tig * 2;
                Ss[r * S_STR + c]           = acc[i][j][0];
                Ss[r * S_STR + c + 1]       = acc[i][j][1];
                Ss[(r + 8) * S_STR + c]     = acc[i][j][2];
                Ss[(r + 8) * S_STR + c + 1] = acc[i][j][3];
            }
    }
    __syncthreads();

    // ---- masked softmax over rows (warp per row, 8 rows per warp) ----
    #pragma unroll
    for (int it = 0; it < 8; it++) {
        int row = warp * 8 + it;
        int qg = q0 + row;
        float dq = (qg < NN) ? Dm[qg] : 1.0f;
        float vals[7];
        float m = -3.0e38f;
        #pragma unroll
        for (int cc = 0; cc < 7; cc++) {
            int c = lane + cc * 32;
            float v;
            if (c >= NN) v = -3.0e38f;
            else {
                float s = Ss[row * S_STR + c];
                bool keep = !mask_active || (c == qg) || (dq > 0.0f && Dm[c] > 0.0f);
                v = keep ? s * 0.125f : -1e9f;
            }
            vals[cc] = v;
            m = fmaxf(m, v);
        }
        #pragma unroll
        for (int o = 16; o > 0; o >>= 1) m = fmaxf(m, __shfl_xor_sync(0xffffffffu, m, o));
        float sum = 0.0f, e[7];
        #pragma unroll
        for (int cc = 0; cc < 7; cc++) { e[cc] = expf(vals[cc] - m); sum += e[cc]; }
        #pragma unroll
        for (int o = 16; o > 0; o >>= 1) sum += __shfl_xor_sync(0xffffffffu, sum, o);
        float inv = 1.0f / sum;
        #pragma unroll
        for (int cc = 0; cc < 7; cc++) Ss[row * S_STR + lane + cc * 32] = e[cc] * inv;
    }
    __syncthreads();

    // ---- O = P V (3xTF32). warps: 4 (rows of 16) x 2 (cols of 32) ----
    {
        int wm = warp >> 1, wn = warp & 1;
        float acc[4][4] = {};
        for (int kk = 0; kk < ANP; kk += 8) {
            unsigned ah[4], al[4];
            int ar = wm * 16 + g;
            #pragma unroll
            for (int v = 0; v < 4; v++) {
                int rr = ar + ((v & 1) ? 8 : 0);
                int cc = kk + tig + ((v >> 1) ? 4 : 0);
                float x = Ss[rr * S_STR + cc];
                unsigned hb = f2tf32(x);
                ah[v] = hb;
                al[v] = f2tf32(x - __uint_as_float(hb));
            }
            unsigned bh[4][2], bl[4][2];
            #pragma unroll
            for (int j = 0; j < 4; j++) {
                int bc = wn * 32 + j * 8 + g;
                #pragma unroll
                for (int v = 0; v < 2; v++) {
                    float x = Vs[(kk + tig + (v ? 4 : 0)) * V_STR + bc];
                    unsigned hb = f2tf32(x);
                    bh[j][v] = hb;
                    bl[j][v] = f2tf32(x - __uint_as_float(hb));
                }
            }
            #pragma unroll
            for (int j = 0; j < 4; j++) {
                mma_tf32(acc[j], ah, bh[j]);
                mma_tf32(acc[j], ah, bl[j]);
                mma_tf32(acc[j], al, bh[j]);
            }
        }
        #pragma unroll
        for (int j = 0; j < 4; j++) {
            int r = q0 + wm * 16 + g;
            int c = h * DHD + wn * 32 + j * 8 + tig * 2;
            if (r < NN) {
                AO[(size_t)(b * NN + r) * CC + c]     = acc[j][0];
                AO[(size_t)(b * NN + r) * CC + c + 1] = acc[j][1];
            }
            if (r + 8 < NN) {
                AO[(size_t)(b * NN + r + 8) * CC + c]     = acc[j][2];
                AO[(size_t)(b * NN + r + 8) * CC + c + 1] = acc[j][3];
            }
        }
    }
}

// ---------------- small kernels ----------------
__global__ void init_prev_kernel(float* prev) {
    int t = blockIdx.x * blockDim.x + threadIdx.x;
    if (t < NPX) prev[t] = 1.0f;
}

__global__ void ln_kernel(const float* __restrict__ in, const float* __restrict__ g,
                          const float* __restrict__ bta, float* __restrict__ out, int mode) {
    int r = blockIdx.x;
    int ir = r;
    if (mode == 1) { int b = r / 196, j = r % 196; ir = b * NN + 1 + j; }
    const float* x = in + (size_t)ir * CC;
    int tid = threadIdx.x;
    __shared__ float red[256];
    float v0 = x[tid], v1 = x[tid + 256], v2 = x[tid + 512];
    float total = block_sum256(v0 + v1 + v2, red);
    float mu = total * (1.0f / CC);
    float d0 = v0 - mu, d1 = v1 - mu, d2 = v2 - mu;
    float tot2 = block_sum256(d0*d0 + d1*d1 + d2*d2, red);
    float rstd = rsqrtf(tot2 * (1.0f / CC) + 1e-5f);
    float* o = out + (size_t)r * CC;
    o[tid]       = d0 * rstd * g[tid]       + bta[tid];
    o[tid + 256] = d1 * rstd * g[tid + 256] + bta[tid + 256];
    o[tid + 512] = d2 * rstd * g[tid + 512] + bta[tid + 512];
}

__global__ void glob_kernel(const float* __restrict__ ph2, const float* __restrict__ prev,
                            float* __restrict__ glob) {
    int b = blockIdx.x;
    int tid = threadIdx.x;
    __shared__ float red[256];
    float pv = (tid < 196) ? prev[b * 196 + tid] : 0.0f;
    float psum = block_sum256(pv, red);
    float denom = psum + 1e-20f;
    for (int c = tid; c < 384; c += 256) {
        float acc = 0.0f;
        for (int j = 0; j < 196; j++)
            acc = fmaf(ph2[((size_t)(b * 196 + j)) * CC + 384 + c], prev[b * 196 + j], acc);
        glob[b * 384 + c] = acc / denom;
    }
}

__global__ void concat_kernel(const float* __restrict__ ph2, const float* __restrict__ glob,
                              float* __restrict__ pcat) {
    size_t t = (size_t)blockIdx.x * blockDim.x + threadIdx.x;
    if (t >= (size_t)NPX * CC) return;
    int c = (int)(t % CC); int row = (int)(t / CC); int b = row / 196;
    pcat[t] = (c < 384) ? ph2[(size_t)row * CC + c] : glob[b * 384 + (c - 384)];
}

__global__ void logits_kernel(const float* __restrict__ ph4, const float* __restrict__ w,
                              const float* __restrict__ bias, float* __restrict__ out) {
    int warp = (blockIdx.x * blockDim.x + threadIdx.x) >> 5;
    int lane = threadIdx.x & 31;
    if (warp >= NPX) return;
    const float* row = ph4 + (size_t)warp * 192;
    float a0 = 0.0f, a1 = 0.0f;
    for (int c = lane; c < 192; c += 32) {
        float h = row[c];
        a0 = fmaf(h, w[c * 2], a0);
        a1 = fmaf(h, w[c * 2 + 1], a1);
    }
    #pragma unroll
    for (int o = 16; o > 0; o >>= 1) {
        a0 += __shfl_down_sync(0xffffffffu, a0, o);
        a1 += __shfl_down_sync(0xffffffffu, a1, o);
    }
    if (lane == 0) {
        out[warp * 2]     = a0 + bias[0];
        out[warp * 2 + 1] = a1 + bias[1];
    }
}

__global__ void decision_kernel(const float* __restrict__ logits, float* __restrict__ prev,
                                float* __restrict__ dfull, unsigned k0, unsigned k1) {
    int t = blockIdx.x * blockDim.x + threadIdx.x;
    if (t >= NPX) return;
    int b = t / 196, j = t % 196;
    float l0 = logits[t * 2], l1 = logits[t * 2 + 1];
    float m = fmaxf(l0, l1);
    float e0 = expf(l0 - m), e1 = expf(l1 - m);
    float inv = 1.0f / (e0 + e1);
    float s0 = e0 * inv, s1 = e1 * inv;
    float u0 = jax_uniform_elem(k0, k1, (unsigned)(2 * t));
    float u1 = jax_uniform_elem(k0, k1, (unsigned)(2 * t + 1));
    float g0 = -logf(-logf(u0));
    float g1 = -logf(-logf(u1));
    float a0 = s0 + g0, a1 = s1 + g1;
    float hard1 = (a1 > a0) ? 1.0f : 0.0f;
    float m2 = fmaxf(a0, a1);
    float y0e = expf(a0 - m2), y1e = expf(a1 - m2);
    float ys1 = y1e / (y0e + y1e);
    float y1 = (hard1 + ys1) - ys1;
    float dec = y1 * prev[t];
    prev[t] = dec;
    dfull[b * NN + 1 + j] = dec;
    if (j == 0) dfull[b * NN] = 1.0f;
}

// ---------------- host orchestration ----------------
extern "C" void kernel_launch(void* const* d_in, const int* in_sizes, int n_in,
                              void* d_out, int out_size) {
    const float* x_in   = (const float*)d_in[0];
    const float* ln1_g  = (const float*)d_in[1];
    const float* ln1_b  = (const float*)d_in[2];
    const float* qkv_w  = (const float*)d_in[3];
    const float* qkv_b  = (const float*)d_in[4];
    const float* proj_w = (const float*)d_in[5];
    const float* proj_b = (const float*)d_in[6];
    const float* ln2_g  = (const float*)d_in[7];
    const float* ln2_b  = (const float*)d_in[8];
    const float* mlp_w1 = (const float*)d_in[9];
    const float* mlp_b1 = (const float*)d_in[10];
    const float* mlp_w2 = (const float*)d_in[11];
    const float* mlp_b2 = (const float*)d_in[12];
    const float* p_ln_g = (const float*)d_in[13];
    const float* p_ln_b = (const float*)d_in[14];
    const float* p_in_w = (const float*)d_in[15];
    const float* p_in_b = (const float*)d_in[16];
    const float* p_w1   = (const float*)d_in[17];
    const float* p_b1   = (const float*)d_in[18];
    const float* p_w2   = (const float*)d_in[19];
    const float* p_b2   = (const float*)d_in[20];
    const float* p_w3   = (const float*)d_in[21];
    const float* p_b3   = (const float*)d_in[22];

    float* X = (float*)d_out;   // residual stream lives in d_out

    float *XN, *QKV, *AO, *MLP1, *PH, *PH2, *PCAT, *PH3, *PH4, *LOG, *GLOB, *PREV, *DFULL;
    cudaGetSymbolAddress((void**)&XN,   g_XN);
    cudaGetSymbolAddress((void**)&QKV,  g_QKV);
    cudaGetSymbolAddress((void**)&AO,   g_AO);
    cudaGetSymbolAddress((void**)&MLP1, g_MLP1);
    cudaGetSymbolAddress((void**)&PH,   g_PH);
    cudaGetSymbolAddress((void**)&PH2,  g_PH2);
    cudaGetSymbolAddress((void**)&PCAT, g_PCAT);
    cudaGetSymbolAddress((void**)&PH3,  g_PH3);
    cudaGetSymbolAddress((void**)&PH4,  g_PH4);
    cudaGetSymbolAddress((void**)&LOG,  g_LOG);
    cudaGetSymbolAddress((void**)&GLOB, g_GLOB);
    cudaGetSymbolAddress((void**)&PREV, g_PREV);
    cudaGetSymbolAddress((void**)&DFULL,g_DFULL);

    cudaFuncSetAttribute(tgemm<0,0>, cudaFuncAttributeMaxDynamicSharedMemorySize, TG_SMEMB);
    cudaFuncSetAttribute(tgemm<1,0>, cudaFuncAttributeMaxDynamicSharedMemorySize, TG_SMEMB);
    cudaFuncSetAttribute(tgemm<0,1>, cudaFuncAttributeMaxDynamicSharedMemorySize, TG_SMEMB);
    cudaFuncSetAttribute(attn_kernel, cudaFuncAttributeMaxDynamicSharedMemorySize, ATT_SMEMB);

    cudaMemcpyAsync(X, x_in, sizeof(float) * (size_t)NT * CC, cudaMemcpyDeviceToDevice);
    init_prev_kernel<<<(NPX + 255) / 256, 256>>>(PREV);

    int p = 0;
    int mask_active = 0;

    for (int i = 0; i < 12; i++) {
        if (i == 3 || i == 6 || i == 9) {
            unsigned fk0, fk1;
            tf2x32(0u, 42u, 0u, (unsigned)p, fk0, fk1);

            ln_kernel<<<NPX, 256>>>(X, p_ln_g + p * CC, p_ln_b + p * CC, PH, 1);
            tgemm<1, 0><<<dim3(CC / 64, (NPX + 127) / 128), 256, TG_SMEMB>>>(
                PH, p_in_w + (size_t)p * CC * CC, p_in_b + p * CC, nullptr, PH2, NPX, CC, CC);
            glob_kernel<<<BB, 256>>>(PH2, PREV, GLOB);
            concat_kernel<<<((size_t)NPX * CC + 255) / 256, 256>>>(PH2, GLOB, PCAT);
            tgemm<1, 0><<<dim3(384 / 64, (NPX + 127) / 128), 256, TG_SMEMB>>>(
                PCAT, p_w1 + (size_t)p * CC * 384, p_b1 + p * 384, nullptr, PH3, NPX, 384, CC);
            tgemm<1, 0><<<dim3(192 / 64, (NPX + 127) / 128), 256, TG_SMEMB>>>(
                PH3, p_w2 + (size_t)p * 384 * 192, p_b2 + p * 192, nullptr, PH4, NPX, 192, 384);
            logits_kernel<<<NPX / 8, 256>>>(PH4, p_w3 + (size_t)p * 192 * 2, p_b3 + p * 2, LOG);
            decision_kernel<<<(NPX + 255) / 256, 256>>>(LOG, PREV, DFULL, fk0, fk1);
            mask_active = 1;
            p++;
        }

        // attention block
        ln_kernel<<<NT, 256>>>(X, ln1_g + i * CC, ln1_b + i * CC, XN, 0);
        tgemm<0, 0><<<dim3(CQ / 64, (NT + 127) / 128), 256, TG_SMEMB>>>(
            XN, qkv_w + (size_t)i * CC * CQ, qkv_b + i * CQ, nullptr, QKV, NT, CQ, CC);
        attn_kernel<<<dim3(4, HH, BB), 256, ATT_SMEMB>>>(QKV, DFULL, AO, mask_active);
        tgemm<0, 1><<<dim3(CC / 64, (NT + 127) / 128), 256, TG_SMEMB>>>(
            AO, proj_w + (size_t)i * CC * CC, proj_b + i * CC, X, X, NT, CC, CC);

        // MLP block
        ln_kernel<<<NT, 256>>>(X, ln2_g + i * CC, ln2_b + i * CC, XN, 0);
        tgemm<1, 0><<<dim3(MM / 64, (NT + 127) / 128), 256, TG_SMEMB>>>(
            XN, mlp_w1 + (size_t)i * CC * MM, mlp_b1 + i * MM, nullptr, MLP1, NT, MM, CC);
        tgemm<0, 1><<<dim3(CC / 64, (NT + 127) / 128), 256, TG_SMEMB>>>(
            MLP1, mlp_w2 + (size_t)i * MM * CC, mlp_b2 + i * CC, X, X, NT, CC, MM);
    }
}